// round 1
// baseline (speedup 1.0000x reference)
#include <cuda_runtime.h>
#include <cuda_fp16.h>
#include <math.h>

#define B_BATCH 64
#define S_DIM   576
#define D_DIM   1024

// Scratch (no allocs allowed): A = [C_L (L rows) ; M (L rows)] row-major 576 wide.
__device__ float g_A[1152 * 576];     // 2.65 MB
__device__ float g_ClT[576 * 576];    // ClT[l*L + k] = Cl[k,l]

// Emulate jnp fp32: arg = f32(pi/n) * (f32(i)+0.5) * f32(k), each op rounded in fp32.
// cos evaluated in double of the fp32 arg (matches accurate cosf, robust to fast-math).
__device__ __forceinline__ float dct_entry(int n, int k, int i) {
    float a   = (float)(M_PI / (double)n);
    float t   = a * ((float)i + 0.5f);
    float arg = t * (float)k;
    float c   = (float)cos((double)arg);
    float sc  = (k == 0) ? sqrtf(1.0f / (float)n) : sqrtf(2.0f / (float)n);
    return c * sc;
}

__global__ void build_basis(int L) {
    int totalA = L * S_DIM;
    int total  = totalA + L * L;
    for (int i = blockIdx.x * blockDim.x + threadIdx.x; i < total;
         i += gridDim.x * blockDim.x) {
        if (i < totalA) {
            int k = i / S_DIM, s = i - k * S_DIM;
            g_A[k * S_DIM + s] = dct_entry(S_DIM, k, s);
        } else {
            int j = i - totalA;
            int l = j / L, k = j - l * L;
            g_ClT[l * L + k] = dct_entry(L, k, l);   // Cl[k,l]
        }
    }
}

// M[l,s] = sum_k Cl[k,l] * C_L[k,s]  -> written into g_A rows [L, 2L)
__global__ void build_M(int L) {
    __shared__ float Ts[16][16];
    __shared__ float Cs[16][16];
    int s = blockIdx.x * 16 + threadIdx.x;
    int l = blockIdx.y * 16 + threadIdx.y;
    float acc = 0.0f;
    for (int k0 = 0; k0 < L; k0 += 16) {
        int kA = k0 + threadIdx.x;
        Ts[threadIdx.y][threadIdx.x] = (l < L && kA < L) ? g_ClT[l * L + kA] : 0.0f;
        int kB = k0 + threadIdx.y;
        Cs[threadIdx.y][threadIdx.x] = (kB < L && s < S_DIM) ? g_A[kB * S_DIM + s] : 0.0f;
        __syncthreads();
        #pragma unroll
        for (int kk = 0; kk < 16; kk++)
            acc = fmaf(Ts[threadIdx.y][kk], Cs[kk][threadIdx.x], acc);
        __syncthreads();
    }
    if (l < L && s < S_DIM) g_A[(L + l) * S_DIM + s] = acc;
}

// Main batched GEMM: Out[b] = A(2L x 576) @ x[b](576 x 1024)
// rows [0,L)   -> trunc (fp32)
// rows [L,2L)  -> recon (fp32 value of fp16-rounded result)
__global__ __launch_bounds__(256) void gemm_main(const float* __restrict__ x,
                                                 float* __restrict__ out_recon,
                                                 float* __restrict__ out_trunc,
                                                 int L) {
    const int twoL = 2 * L;
    __shared__ float As[8][128];
    __shared__ float Bs[8][128];

    const int tid = threadIdx.x;
    const int b = blockIdx.z;
    const float* __restrict__ Bmat = x + (size_t)b * S_DIM * D_DIM;
    const int rowBase = blockIdx.y * 128;
    const int colBase = blockIdx.x * 128;

    const int aRow = tid >> 1;            // 0..127
    const int aCol = (tid & 1) * 4;       // 0 or 4
    const int bRow = tid >> 5;            // 0..7
    const int bCol = (tid & 31) * 4;      // 0..124

    const int ty = tid >> 4;              // 0..15
    const int tx = tid & 15;              // 0..15

    float acc[8][8];
    #pragma unroll
    for (int i = 0; i < 8; i++)
        #pragma unroll
        for (int j = 0; j < 8; j++) acc[i][j] = 0.0f;

    for (int k0 = 0; k0 < S_DIM; k0 += 8) {
        float4 av;
        const int gr = rowBase + aRow;
        if (gr < twoL)
            av = *reinterpret_cast<const float4*>(&g_A[(size_t)gr * S_DIM + k0 + aCol]);
        else
            av = make_float4(0.f, 0.f, 0.f, 0.f);
        As[aCol + 0][aRow] = av.x;
        As[aCol + 1][aRow] = av.y;
        As[aCol + 2][aRow] = av.z;
        As[aCol + 3][aRow] = av.w;

        float4 bv = *reinterpret_cast<const float4*>(
            &Bmat[(size_t)(k0 + bRow) * D_DIM + colBase + bCol]);
        *reinterpret_cast<float4*>(&Bs[bRow][bCol]) = bv;

        __syncthreads();

        #pragma unroll
        for (int kk = 0; kk < 8; kk++) {
            float4 a0 = *reinterpret_cast<const float4*>(&As[kk][ty * 8]);
            float4 a1 = *reinterpret_cast<const float4*>(&As[kk][ty * 8 + 4]);
            float4 b0 = *reinterpret_cast<const float4*>(&Bs[kk][tx * 8]);
            float4 b1 = *reinterpret_cast<const float4*>(&Bs[kk][tx * 8 + 4]);
            float ar[8] = {a0.x, a0.y, a0.z, a0.w, a1.x, a1.y, a1.z, a1.w};
            float br[8] = {b0.x, b0.y, b0.z, b0.w, b1.x, b1.y, b1.z, b1.w};
            #pragma unroll
            for (int i = 0; i < 8; i++)
                #pragma unroll
                for (int j = 0; j < 8; j++)
                    acc[i][j] = fmaf(ar[i], br[j], acc[i][j]);
        }
        __syncthreads();
    }

    #pragma unroll
    for (int i = 0; i < 8; i++) {
        const int r = rowBase + ty * 8 + i;
        if (r < L) {
            float* dst = out_trunc + ((size_t)b * L + r) * D_DIM + colBase + tx * 8;
            #pragma unroll
            for (int j = 0; j < 8; j += 4) {
                float4 v = make_float4(acc[i][j], acc[i][j + 1], acc[i][j + 2], acc[i][j + 3]);
                *reinterpret_cast<float4*>(dst + j) = v;
            }
        } else if (r < twoL) {
            float* dst = out_recon + ((size_t)b * L + (r - L)) * D_DIM + colBase + tx * 8;
            #pragma unroll
            for (int j = 0; j < 8; j += 4) {
                float4 v;
                v.x = __half2float(__float2half_rn(acc[i][j + 0]));
                v.y = __half2float(__float2half_rn(acc[i][j + 1]));
                v.z = __half2float(__float2half_rn(acc[i][j + 2]));
                v.w = __half2float(__float2half_rn(acc[i][j + 3]));
                *reinterpret_cast<float4*>(dst + j) = v;
            }
        }
    }
}

extern "C" void kernel_launch(void* const* d_in, const int* in_sizes, int n_in,
                              void* d_out, int out_size) {
    const float* x = (const float*)d_in[0];

    // out = concat(recon[64,L,1024] fp16->f32, trunc[64,L,1024] f32) => 131072*L elems
    const int L = out_size / (2 * B_BATCH * D_DIM);

    float* out_recon = (float*)d_out;
    float* out_trunc = (float*)d_out + (size_t)B_BATCH * L * D_DIM;

    build_basis<<<256, 256>>>(L);

    dim3 mthreads(16, 16);
    dim3 mgrid((S_DIM + 15) / 16, (L + 15) / 16);
    build_M<<<mgrid, mthreads>>>(L);

    dim3 grid(D_DIM / 128, (2 * L + 127) / 128, B_BATCH);
    gemm_main<<<grid, 256>>>(x, out_recon, out_trunc, L);
}

// round 3
// speedup vs baseline: 2.9381x; 2.9381x over previous
#include <cuda_runtime.h>
#include <cuda_fp16.h>
#include <cuda_bf16.h>
#include <math.h>
#include <stdint.h>

#define B_BATCH 64
#define S_DIM   576
#define D_DIM   1024
#define MROWS   1152              // 9 * 128 >= 2L always

// ---------------- scratch (no allocs allowed) ----------------
__device__ float         g_A[MROWS * S_DIM];          // fp32 [C_L ; M]
__device__ float         g_ClT[S_DIM * S_DIM];        // ClT[l*L + k] = Cl[k,l]
__device__ __nv_bfloat16 g_Ah[MROWS * S_DIM];
__device__ __nv_bfloat16 g_Al[MROWS * S_DIM];
__device__ __nv_bfloat16 g_xh[(size_t)B_BATCH * D_DIM * S_DIM];  // transposed [b][d][s]
__device__ __nv_bfloat16 g_xl[(size_t)B_BATCH * D_DIM * S_DIM];

// ---------------- helpers ----------------
__device__ __forceinline__ uint32_t smem_u32(const void* p) {
    uint32_t a;
    asm("{ .reg .u64 t; cvta.to.shared.u64 t, %1; cvt.u32.u64 %0, t; }" : "=r"(a) : "l"(p));
    return a;
}
__device__ __forceinline__ void cp16(uint32_t dst, const void* src) {
    asm volatile("cp.async.cg.shared.global [%0], [%1], 16;" :: "r"(dst), "l"(src));
}
#define CP_COMMIT() asm volatile("cp.async.commit_group;" ::: "memory")
#define CP_WAIT1()  asm volatile("cp.async.wait_group 1;" ::: "memory")

__device__ __forceinline__ void ldsm_x4(uint32_t& r0, uint32_t& r1, uint32_t& r2,
                                        uint32_t& r3, uint32_t addr) {
    asm volatile("ldmatrix.sync.aligned.m8n8.x4.shared.b16 {%0,%1,%2,%3}, [%4];"
                 : "=r"(r0), "=r"(r1), "=r"(r2), "=r"(r3) : "r"(addr));
}
__device__ __forceinline__ void mma16816(float* d, const uint32_t* a,
                                         uint32_t b0, uint32_t b1) {
    asm volatile("mma.sync.aligned.m16n8k16.row.col.f32.bf16.bf16.f32 "
                 "{%0,%1,%2,%3}, {%4,%5,%6,%7}, {%8,%9}, {%0,%1,%2,%3};"
                 : "+f"(d[0]), "+f"(d[1]), "+f"(d[2]), "+f"(d[3])
                 : "r"(a[0]), "r"(a[1]), "r"(a[2]), "r"(a[3]), "r"(b0), "r"(b1));
}

#define SWZ(x) ((x) ^ (((x) >> 3) & 0x70))

// ---------------- basis build ----------------
__device__ __forceinline__ float dct_entry(int n, int k, int i) {
    float a   = (float)(M_PI / (double)n);
    float t   = a * ((float)i + 0.5f);
    float arg = t * (float)k;
    float c   = (float)cos((double)arg);
    float sc  = (k == 0) ? sqrtf(1.0f / (float)n) : sqrtf(2.0f / (float)n);
    return c * sc;
}

__global__ void build_basis(int L) {
    int totalA = L * S_DIM;
    int total  = totalA + L * L;
    for (int i = blockIdx.x * blockDim.x + threadIdx.x; i < total;
         i += gridDim.x * blockDim.x) {
        if (i < totalA) {
            int k = i / S_DIM, s = i - k * S_DIM;
            g_A[k * S_DIM + s] = dct_entry(S_DIM, k, s);
        } else {
            int j = i - totalA;
            int l = j / L, k = j - l * L;
            g_ClT[l * L + k] = dct_entry(L, k, l);
        }
    }
}

// M[l,s] = sum_k Cl[k,l] * C_L[k,s] -> g_A rows [L, 2L). 32x32 tile, 2x2 per thread.
__global__ void build_M(int L) {
    __shared__ float Ts[32][33];
    __shared__ float Cs[32][33];
    int tx = threadIdx.x, ty = threadIdx.y;        // 16x16
    int lin = ty * 16 + tx;
    int l0 = blockIdx.y * 32, s0 = blockIdx.x * 32;
    float acc00 = 0.f, acc01 = 0.f, acc10 = 0.f, acc11 = 0.f;
    for (int k0 = 0; k0 < L; k0 += 32) {
        #pragma unroll
        for (int q = 0; q < 4; q++) {
            int e = lin + q * 256;
            int i = e >> 5, j = e & 31;
            int l = l0 + i, k = k0 + j;
            Ts[i][j] = (l < L && k < L) ? g_ClT[l * L + k] : 0.0f;
            int kk = k0 + i, s = s0 + j;
            Cs[i][j] = (kk < L && s < S_DIM) ? g_A[kk * S_DIM + s] : 0.0f;
        }
        __syncthreads();
        #pragma unroll
        for (int kk = 0; kk < 32; kk++) {
            float a0 = Ts[ty * 2][kk], a1 = Ts[ty * 2 + 1][kk];
            float b0 = Cs[kk][tx * 2], b1 = Cs[kk][tx * 2 + 1];
            acc00 = fmaf(a0, b0, acc00); acc01 = fmaf(a0, b1, acc01);
            acc10 = fmaf(a1, b0, acc10); acc11 = fmaf(a1, b1, acc11);
        }
        __syncthreads();
    }
    int l = l0 + ty * 2, s = s0 + tx * 2;
    if (l < L     && s < S_DIM)     g_A[(L + l) * S_DIM + s]         = acc00;
    if (l < L     && s + 1 < S_DIM) g_A[(L + l) * S_DIM + s + 1]     = acc01;
    if (l + 1 < L && s < S_DIM)     g_A[(L + l + 1) * S_DIM + s]     = acc10;
    if (l + 1 < L && s + 1 < S_DIM) g_A[(L + l + 1) * S_DIM + s + 1] = acc11;
}

__global__ void convert_A(int L) {
    int i = blockIdx.x * blockDim.x + threadIdx.x;
    if (i < MROWS * S_DIM) {
        int row = i / S_DIM;
        float v = (row < 2 * L) ? g_A[i] : 0.0f;   // zero pad rows beyond 2L
        __nv_bfloat16 h = __float2bfloat16(v);
        g_Ah[i] = h;
        g_Al[i] = __float2bfloat16(v - __bfloat162float(h));
    }
}

// x[b][s][d] fp32 -> g_xh/g_xl[b][d][s] bf16 (transposed, hi/lo split)
__global__ void convert_x(const float* __restrict__ x) {
    __shared__ float t[32][33];
    int b = blockIdx.z;
    int s0 = blockIdx.x * 32, d0 = blockIdx.y * 32;
    int lane = threadIdx.x & 31, row8 = threadIdx.x >> 5;
    #pragma unroll
    for (int r = 0; r < 4; r++) {
        int i = row8 + 8 * r;
        t[i][lane] = x[((size_t)b * S_DIM + s0 + i) * D_DIM + d0 + lane];
    }
    __syncthreads();
    #pragma unroll
    for (int r = 0; r < 4; r++) {
        int i = row8 + 8 * r;              // d index within tile
        float v = t[lane][i];
        __nv_bfloat16 h = __float2bfloat16(v);
        __nv_bfloat16 l = __float2bfloat16(v - __bfloat162float(h));
        size_t idx = ((size_t)b * D_DIM + d0 + i) * S_DIM + s0 + lane;
        g_xh[idx] = h;
        g_xl[idx] = l;
    }
}

// ---------------- main HMMA GEMM ----------------
// Out[b] = A(1152 x 1728cat) @ x[b](1728cat x 1024), K = 3 terms x 576
#define BK          64
#define STAGES      3
#define STAGE_BYTES 32768          // A 16KB + B 16KB
#define SMEM_G      (STAGES * STAGE_BYTES)   // 98304
#define KITERS      27             // 3 terms * 9 chunks of 64

__device__ __forceinline__ void load_stage(uint32_t sbase, int slot, int j,
                                           int rowBase, int colBase, int b, int tid) {
    int p  = j / 9;                 // 0: Ah*Bh  1: Ah*Bl  2: Al*Bh
    int k0 = (j - p * 9) * 64;
    const __nv_bfloat16* Asrc = (p < 2) ? g_Ah : g_Al;
    const __nv_bfloat16* Bsrc = (p == 1) ? g_xl : g_xh;
    uint32_t sA = sbase + slot * STAGE_BYTES;
    uint32_t sB = sA + 16384;
    #pragma unroll
    for (int q = 0; q < 4; q++) {
        int c = tid + q * 256;
        int row = c >> 3, ku = c & 7;
        cp16(sA + SWZ(row * 128 + ku * 16),
             Asrc + (size_t)(rowBase + row) * S_DIM + k0 + ku * 8);
        cp16(sB + SWZ(row * 128 + ku * 16),
             Bsrc + ((size_t)b * D_DIM + colBase + row) * S_DIM + k0 + ku * 8);
    }
}

__global__ __launch_bounds__(256, 2) void gemm_mma(float* __restrict__ out_recon,
                                                   float* __restrict__ out_trunc,
                                                   int L) {
    extern __shared__ char dsm[];
    uint32_t sbase = smem_u32(dsm);
    const int tid  = threadIdx.x;
    const int warp = tid >> 5;
    const int lane = tid & 31;
    const int b = blockIdx.z;
    const int rowBase = blockIdx.y * 128;
    const int colBase = blockIdx.x * 128;

    const int mBase = (warp & 1) * 64;   // 2 warps in M
    const int nBase = (warp >> 1) * 32;  // 4 warps in N

    float acc[4][4][4];
    #pragma unroll
    for (int mt = 0; mt < 4; mt++)
        #pragma unroll
        for (int nt = 0; nt < 4; nt++)
            #pragma unroll
            for (int i = 0; i < 4; i++) acc[mt][nt][i] = 0.0f;

    // prologue
    load_stage(sbase, 0, 0, rowBase, colBase, b, tid); CP_COMMIT();
    load_stage(sbase, 1, 1, rowBase, colBase, b, tid); CP_COMMIT();

    // precompute lane address components
    const int aRow  = lane & 15;
    const int aColB = (lane >> 4) * 16;                 // bytes
    const int bRow  = (lane & 7) + ((lane >> 4) & 1) * 8;
    const int bColB = ((lane >> 3) & 1) * 16;           // bytes

    for (int i = 0; i < KITERS; i++) {
        int slot = i % 3;
        CP_WAIT1();
        __syncthreads();

        uint32_t sA = sbase + slot * STAGE_BYTES;
        uint32_t sB = sA + 16384;

        #pragma unroll
        for (int ks = 0; ks < 4; ks++) {
            uint32_t afr[4][4];
            #pragma unroll
            for (int mt = 0; mt < 4; mt++) {
                int off = (mBase + mt * 16 + aRow) * 128 + ks * 32 + aColB;
                ldsm_x4(afr[mt][0], afr[mt][1], afr[mt][2], afr[mt][3],
                        sA + SWZ(off));
            }
            uint32_t bfr[8];
            #pragma unroll
            for (int nt2 = 0; nt2 < 2; nt2++) {
                int off = (nBase + nt2 * 16 + bRow) * 128 + ks * 32 + bColB;
                ldsm_x4(bfr[nt2 * 4 + 0], bfr[nt2 * 4 + 1],
                        bfr[nt2 * 4 + 2], bfr[nt2 * 4 + 3], sB + SWZ(off));
            }
            #pragma unroll
            for (int mt = 0; mt < 4; mt++)
                #pragma unroll
                for (int nt = 0; nt < 4; nt++)
                    mma16816(acc[mt][nt], afr[mt], bfr[nt * 2], bfr[nt * 2 + 1]);
        }

        int j = i + 2;
        if (j < KITERS) load_stage(sbase, j % 3, j, rowBase, colBase, b, tid);
        CP_COMMIT();   // always commit: keeps wait_group accounting uniform
    }

    // ---------------- epilogue ----------------
    const int twoL = 2 * L;
    #pragma unroll
    for (int mt = 0; mt < 4; mt++) {
        #pragma unroll
        for (int nt = 0; nt < 4; nt++) {
            int rA = rowBase + mBase + mt * 16 + (lane >> 2);
            int cc = colBase + nBase + nt * 8 + (lane & 3) * 2;
            #pragma unroll
            for (int h = 0; h < 2; h++) {
                int r = rA + h * 8;
                float v0 = acc[mt][nt][h * 2 + 0];
                float v1 = acc[mt][nt][h * 2 + 1];
                if (r < L) {
                    float2 v = make_float2(v0, v1);
                    *reinterpret_cast<float2*>(
                        &out_trunc[((size_t)b * L + r) * D_DIM + cc]) = v;
                } else if (r < twoL) {
                    float2 v = make_float2(__half2float(__float2half_rn(v0)),
                                           __half2float(__float2half_rn(v1)));
                    *reinterpret_cast<float2*>(
                        &out_recon[((size_t)b * L + (r - L)) * D_DIM + cc]) = v;
                }
            }
        }
    }
}

// ---------------- launch ----------------
extern "C" void kernel_launch(void* const* d_in, const int* in_sizes, int n_in,
                              void* d_out, int out_size) {
    const float* x = (const float*)d_in[0];
    const int L = out_size / (2 * B_BATCH * D_DIM);

    float* out_recon = (float*)d_out;
    float* out_trunc = (float*)d_out + (size_t)B_BATCH * L * D_DIM;

    // idempotent, host-side only (not a stream op): safe under graph capture
    cudaFuncSetAttribute(gemm_mma, cudaFuncAttributeMaxDynamicSharedMemorySize, SMEM_G);

    build_basis<<<512, 256>>>(L);
    dim3 mgrid((S_DIM + 31) / 32, (L + 31) / 32);
    build_M<<<mgrid, dim3(16, 16)>>>(L);
    convert_A<<<(MROWS * S_DIM + 255) / 256, 256>>>(L);
    convert_x<<<dim3(S_DIM / 32, D_DIM / 32, B_BATCH), 256>>>(x);

    dim3 grid(D_DIM / 128, MROWS / 128, B_BATCH);
    gemm_mma<<<grid, 256, SMEM_G>>>(out_recon, out_trunc, L);
}

// round 5
// speedup vs baseline: 4.0618x; 1.3824x over previous
#include <cuda_runtime.h>
#include <cuda_fp16.h>
#include <cuda_bf16.h>
#include <math.h>
#include <stdint.h>

#define B_BATCH 64
#define S_DIM   576
#define SH      288            // folded K (e/o each)
#define D_DIM   1024
#define AROWS   640            // padded rows per parity: [trunc(<=288) | pad | M at 320..320+nM]
#define MOFF    320            // row offset of Me/Mo block

// ---------------- scratch (no allocs allowed) ----------------
__device__ float         g_A2[2 * AROWS * SH];        // fp32 [Ce;pad;Me] / [Co;pad;Mo]
__device__ float         g_ClT[S_DIM * S_DIM];        // ClT[i*L + k] = Cl[k,i]
__device__ __nv_bfloat16 g_Ah2[2 * AROWS * SH];
__device__ __nv_bfloat16 g_Al2[2 * AROWS * SH];
__device__ __nv_bfloat16 g_Bh[(size_t)2 * B_BATCH * D_DIM * SH];  // [p][b][d][s]
__device__ __nv_bfloat16 g_Bl[(size_t)2 * B_BATCH * D_DIM * SH];
__device__ float         g_y[(size_t)2 * B_BATCH * SH * D_DIM];   // ye / yo scratch

// ---------------- helpers ----------------
__device__ __forceinline__ uint32_t smem_u32(const void* p) {
    uint32_t a;
    asm("{ .reg .u64 t; cvta.to.shared.u64 t, %1; cvt.u32.u64 %0, t; }" : "=r"(a) : "l"(p));
    return a;
}
__device__ __forceinline__ void cp16(uint32_t dst, const void* src) {
    asm volatile("cp.async.cg.shared.global [%0], [%1], 16;" :: "r"(dst), "l"(src));
}
#define CP_COMMIT() asm volatile("cp.async.commit_group;" ::: "memory")
#define CP_WAIT1()  asm volatile("cp.async.wait_group 1;" ::: "memory")

__device__ __forceinline__ void ldsm_x4(uint32_t& r0, uint32_t& r1, uint32_t& r2,
                                        uint32_t& r3, uint32_t addr) {
    asm volatile("ldmatrix.sync.aligned.m8n8.x4.shared.b16 {%0,%1,%2,%3}, [%4];"
                 : "=r"(r0), "=r"(r1), "=r"(r2), "=r"(r3) : "r"(addr));
}
__device__ __forceinline__ void mma16816(float* d, const uint32_t* a,
                                         uint32_t b0, uint32_t b1) {
    asm volatile("mma.sync.aligned.m16n8k16.row.col.f32.bf16.bf16.f32 "
                 "{%0,%1,%2,%3}, {%4,%5,%6,%7}, {%8,%9}, {%0,%1,%2,%3};"
                 : "+f"(d[0]), "+f"(d[1]), "+f"(d[2]), "+f"(d[3])
                 : "r"(a[0]), "r"(a[1]), "r"(a[2]), "r"(a[3]), "r"(b0), "r"(b1));
}
#define SWZ(x) ((x) ^ (((x) >> 3) & 0x70))

// ---------------- basis build ----------------
__device__ __forceinline__ float dct_entry(int n, int k, int i) {
    float a   = (float)(M_PI / (double)n);
    float t   = a * ((float)i + 0.5f);
    float arg = t * (float)k;
    float c   = (float)cos((double)arg);
    float sc  = (k == 0) ? sqrtf(1.0f / (float)n) : sqrtf(2.0f / (float)n);
    return c * sc;
}

__global__ void zero_A2() {
    int n = 2 * AROWS * SH;
    for (int i = blockIdx.x * blockDim.x + threadIdx.x; i < n;
         i += gridDim.x * blockDim.x) g_A2[i] = 0.0f;
}

// fill C-half rows (trunc part) + ClT
__global__ void build_basis2(int L) {
    int totalC = L * SH;          // C[k, s<288] -> A2[k&1][k>>1][s]
    int total  = totalC + L * L;  // ClT[i*L+k] = Cl[k,i]
    for (int i = blockIdx.x * blockDim.x + threadIdx.x; i < total;
         i += gridDim.x * blockDim.x) {
        if (i < totalC) {
            int k = i / SH, s = i - k * SH;
            g_A2[(size_t)(k & 1) * AROWS * SH + (size_t)(k >> 1) * SH + s] =
                dct_entry(S_DIM, k, s);
        } else {
            int j = i - totalC;
            int ii = j / L, k = j - ii * L;
            g_ClT[ii * L + k] = dct_entry(L, k, ii);
        }
    }
}

// Mp[l,s] = sum_{k=2j+p < L} Cl[k,l] * C[k,s]  ->  A2[p][MOFF+l][s]
__global__ void build_M2(int L, int nM) {
    __shared__ float Ts[32][33];   // Ts[ii][jj] = Cl[2(k0+jj)+p, l0+ii]
    __shared__ float Cs[32][33];   // Cs[jj][ss] = C[2(k0+jj)+p, s0+ss]
    int p = blockIdx.z;
    int nK = (L + 1 - p) >> 1;     // # k of parity p below L
    const float* Cbase = g_A2 + (size_t)p * AROWS * SH;
    int tx = threadIdx.x, ty = threadIdx.y;       // 16x16
    int lin = ty * 16 + tx;
    int l0 = blockIdx.y * 32, s0 = blockIdx.x * 32;
    float acc00 = 0.f, acc01 = 0.f, acc10 = 0.f, acc11 = 0.f;
    for (int k0 = 0; k0 < nK; k0 += 32) {
        #pragma unroll
        for (int q = 0; q < 4; q++) {
            int e = lin + q * 256;
            int i = e >> 5, j = e & 31;
            int l = l0 + i, jj = k0 + j;
            Ts[i][j] = (l < nM && jj < nK) ? g_ClT[l * L + 2 * jj + p] : 0.0f;
            int j2 = k0 + i, s = s0 + j;
            Cs[i][j] = (j2 < nK && s < SH) ? Cbase[(size_t)j2 * SH + s] : 0.0f;
        }
        __syncthreads();
        #pragma unroll
        for (int kk = 0; kk < 32; kk++) {
            float a0 = Ts[ty * 2][kk], a1 = Ts[ty * 2 + 1][kk];
            float b0 = Cs[kk][tx * 2], b1 = Cs[kk][tx * 2 + 1];
            acc00 = fmaf(a0, b0, acc00); acc01 = fmaf(a0, b1, acc01);
            acc10 = fmaf(a1, b0, acc10); acc11 = fmaf(a1, b1, acc11);
        }
        __syncthreads();
    }
    float* Obase = g_A2 + (size_t)p * AROWS * SH + (size_t)MOFF * SH;
    int l = l0 + ty * 2, s = s0 + tx * 2;
    if (l < nM     && s < SH)     Obase[(size_t)l * SH + s]           = acc00;
    if (l < nM     && s + 1 < SH) Obase[(size_t)l * SH + s + 1]       = acc01;
    if (l + 1 < nM && s < SH)     Obase[(size_t)(l + 1) * SH + s]     = acc10;
    if (l + 1 < nM && s + 1 < SH) Obase[(size_t)(l + 1) * SH + s + 1] = acc11;
}

__global__ void convert_A2() {
    int n = 2 * AROWS * SH;
    for (int i = blockIdx.x * blockDim.x + threadIdx.x; i < n;
         i += gridDim.x * blockDim.x) {
        float v = g_A2[i];
        __nv_bfloat16 h = __float2bfloat16(v);
        g_Ah2[i] = h;
        g_Al2[i] = __float2bfloat16(v - __bfloat162float(h));
    }
}

// x[b][s][d] fp32 -> e/o fold + transpose + hi/lo split: g_B?[p][b][d][s<288]
__global__ void fold_x(const float* __restrict__ x) {
    __shared__ float t0[32][33];
    __shared__ float t1[32][33];
    int b = blockIdx.z;
    int s0 = blockIdx.x * 32, d0 = blockIdx.y * 32;
    int lane = threadIdx.x & 31, row8 = threadIdx.x >> 5;
    #pragma unroll
    for (int r = 0; r < 4; r++) {
        int i = row8 + 8 * r;
        t0[i][lane] = x[((size_t)b * S_DIM + s0 + i) * D_DIM + d0 + lane];
        t1[i][lane] = x[((size_t)b * S_DIM + (S_DIM - 1 - (s0 + i))) * D_DIM + d0 + lane];
    }
    __syncthreads();
    #pragma unroll
    for (int r = 0; r < 4; r++) {
        int i = row8 + 8 * r;                 // d index within tile
        float a = t0[lane][i], c = t1[lane][i];
        float e = a + c, o = a - c;
        __nv_bfloat16 eh = __float2bfloat16(e);
        __nv_bfloat16 el = __float2bfloat16(e - __bfloat162float(eh));
        __nv_bfloat16 oh = __float2bfloat16(o);
        __nv_bfloat16 ol = __float2bfloat16(o - __bfloat162float(oh));
        size_t de = ((size_t)b * D_DIM + d0 + i) * SH + s0 + lane;
        size_t doff = ((size_t)(B_BATCH + b) * D_DIM + d0 + i) * SH + s0 + lane;
        g_Bh[de]   = eh;  g_Bl[de]   = el;
        g_Bh[doff] = oh;  g_Bl[doff] = ol;
    }
}

// ---------------- main HMMA GEMM ----------------
// per parity p: Out = A_p(640 x 288, 3 hi/lo terms) @ B_p(288 x 1024) per batch
#define BK          48
#define STAGES      3
#define STAGE_BYTES 32768          // A 16KB (128 rows x 128B stride) + B 16KB
#define SMEM_G      (STAGES * STAGE_BYTES)
#define KITERS      18             // 3 terms * 6 chunks of 48

__device__ __forceinline__ void load_stage(uint32_t sbase, int slot, int j,
                                           int rowBase, int colBase,
                                           const __nv_bfloat16* Ah,
                                           const __nv_bfloat16* Al,
                                           const __nv_bfloat16* Bh,
                                           const __nv_bfloat16* Bl, int tid) {
    int t  = j / 6;                 // 0: Ah*Bh  1: Ah*Bl  2: Al*Bh
    int k0 = (j - t * 6) * BK;
    const __nv_bfloat16* Asrc = (t < 2) ? Ah : Al;
    const __nv_bfloat16* Bsrc = (t == 1) ? Bl : Bh;
    uint32_t sA = sbase + slot * STAGE_BYTES;
    uint32_t sB = sA + 16384;
    #pragma unroll
    for (int q = 0; q < 3; q++) {          // 768 chunks of 16B each side
        int c = tid + q * 256;
        int row = c / 6, ku = c % 6;
        cp16(sA + SWZ(row * 128 + ku * 16),
             Asrc + (size_t)(rowBase + row) * SH + k0 + ku * 8);
        cp16(sB + SWZ(row * 128 + ku * 16),
             Bsrc + (size_t)(colBase + row) * SH + k0 + ku * 8);
    }
}

__global__ __launch_bounds__(256, 2) void gemm_mma(float* __restrict__ out_trunc,
                                                   int L, int nM) {
    extern __shared__ char dsm[];
    uint32_t sbase = smem_u32(dsm);
    const int tid  = threadIdx.x;
    const int warp = tid >> 5;
    const int lane = tid & 31;
    const int b = blockIdx.z;
    const int p = blockIdx.y / 5;
    const int rowBase = (blockIdx.y % 5) * 128;
    const int colBase = blockIdx.x * 128;
    const int nT = (L + 1 - p) >> 1;       // # trunc rows of this parity

    const __nv_bfloat16* Ah = g_Ah2 + (size_t)p * AROWS * SH;
    const __nv_bfloat16* Al = g_Al2 + (size_t)p * AROWS * SH;
    const __nv_bfloat16* Bh = g_Bh + ((size_t)p * B_BATCH + b) * D_DIM * SH;
    const __nv_bfloat16* Bl = g_Bl + ((size_t)p * B_BATCH + b) * D_DIM * SH;

    const int mBase = (warp & 1) * 64;   // 2 warps in M
    const int nBase = (warp >> 1) * 32;  // 4 warps in N

    float acc[4][4][4];
    #pragma unroll
    for (int mt = 0; mt < 4; mt++)
        #pragma unroll
        for (int nt = 0; nt < 4; nt++)
            #pragma unroll
            for (int i = 0; i < 4; i++) acc[mt][nt][i] = 0.0f;

    load_stage(sbase, 0, 0, rowBase, colBase, Ah, Al, Bh, Bl, tid); CP_COMMIT();
    load_stage(sbase, 1, 1, rowBase, colBase, Ah, Al, Bh, Bl, tid); CP_COMMIT();

    const int aRow  = lane & 15;
    const int aColB = (lane >> 4) * 16;
    const int bRow  = (lane & 7) + ((lane >> 4) & 1) * 8;
    const int bColB = ((lane >> 3) & 1) * 16;

    for (int i = 0; i < KITERS; i++) {
        int slot = i % 3;
        CP_WAIT1();
        __syncthreads();

        uint32_t sA = sbase + slot * STAGE_BYTES;
        uint32_t sB = sA + 16384;

        #pragma unroll
        for (int ks = 0; ks < 3; ks++) {
            uint32_t afr[4][4];
            #pragma unroll
            for (int mt = 0; mt < 4; mt++) {
                int off = (mBase + mt * 16 + aRow) * 128 + ks * 32 + aColB;
                ldsm_x4(afr[mt][0], afr[mt][1], afr[mt][2], afr[mt][3], sA + SWZ(off));
            }
            uint32_t bfr[8];
            #pragma unroll
            for (int nt2 = 0; nt2 < 2; nt2++) {
                int off = (nBase + nt2 * 16 + bRow) * 128 + ks * 32 + bColB;
                ldsm_x4(bfr[nt2 * 4 + 0], bfr[nt2 * 4 + 1],
                        bfr[nt2 * 4 + 2], bfr[nt2 * 4 + 3], sB + SWZ(off));
            }
            #pragma unroll
            for (int mt = 0; mt < 4; mt++)
                #pragma unroll
                for (int nt = 0; nt < 4; nt++)
                    mma16816(acc[mt][nt], afr[mt], bfr[nt * 2], bfr[nt * 2 + 1]);
        }

        int j = i + 2;
        if (j < KITERS)
            load_stage(sbase, j % 3, j, rowBase, colBase, Ah, Al, Bh, Bl, tid);
        CP_COMMIT();
    }

    // ---------------- epilogue ----------------
    float* ybase = g_y + ((size_t)p * B_BATCH + b) * SH * D_DIM;
    #pragma unroll
    for (int mt = 0; mt < 4; mt++) {
        #pragma unroll
        for (int nt = 0; nt < 4; nt++) {
            int rA = rowBase + mBase + mt * 16 + (lane >> 2);
            int cc = colBase + nBase + nt * 8 + (lane & 3) * 2;
            #pragma unroll
            for (int h = 0; h < 2; h++) {
                int r = rA + h * 8;
                float2 v = make_float2(acc[mt][nt][h * 2 + 0], acc[mt][nt][h * 2 + 1]);
                if (r < nT) {
                    int tr = 2 * r + p;
                    *reinterpret_cast<float2*>(
                        &out_trunc[((size_t)b * L + tr) * D_DIM + cc]) = v;
                } else if (r >= MOFF && r < MOFF + nM) {
                    *reinterpret_cast<float2*>(
                        &ybase[(size_t)(r - MOFF) * D_DIM + cc]) = v;
                }
            }
        }
    }
}

// recon[l] = fp16(ye+yo), recon[L-1-l] = fp16(ye-yo)
__global__ void butterfly(float* __restrict__ out_recon, int L, int nM) {
    int idx = blockIdx.x * blockDim.x + threadIdx.x;
    int total = B_BATCH * nM * (D_DIM / 4);
    if (idx >= total) return;
    int d4 = idx & (D_DIM / 4 - 1);
    int l  = (idx / (D_DIM / 4)) % nM;
    int b  = idx / ((D_DIM / 4) * nM);
    int d  = d4 * 4;
    const float4 ye = *reinterpret_cast<const float4*>(
        &g_y[((size_t)b * SH + l) * D_DIM + d]);
    const float4 yo = *reinterpret_cast<const float4*>(
        &g_y[((size_t)(B_BATCH + b) * SH + l) * D_DIM + d]);
    float4 s, f;
    s.x = __half2float(__float2half_rn(ye.x + yo.x));
    s.y = __half2float(__float2half_rn(ye.y + yo.y));
    s.z = __half2float(__float2half_rn(ye.z + yo.z));
    s.w = __half2float(__float2half_rn(ye.w + yo.w));
    *reinterpret_cast<float4*>(&out_recon[((size_t)b * L + l) * D_DIM + d]) = s;
    int l2 = L - 1 - l;
    if (l2 != l) {
        f.x = __half2float(__float2half_rn(ye.x - yo.x));
        f.y = __half2float(__float2half_rn(ye.y - yo.y));
        f.z = __half2float(__float2half_rn(ye.z - yo.z));
        f.w = __half2float(__float2half_rn(ye.w - yo.w));
        *reinterpret_cast<float4*>(&out_recon[((size_t)b * L + l2) * D_DIM + d]) = f;
    }
}

// ---------------- launch ----------------
extern "C" void kernel_launch(void* const* d_in, const int* in_sizes, int n_in,
                              void* d_out, int out_size) {
    const float* x = (const float*)d_in[0];
    const int L  = out_size / (2 * B_BATCH * D_DIM);
    const int nM = (L + 1) >> 1;

    float* out_recon = (float*)d_out;
    float* out_trunc = (float*)d_out + (size_t)B_BATCH * L * D_DIM;

    cudaFuncSetAttribute(gemm_mma, cudaFuncAttributeMaxDynamicSharedMemorySize, SMEM_G);

    zero_A2<<<128, 256>>>();
    build_basis2<<<512, 256>>>(L);
    build_M2<<<dim3(SH / 32, (nM + 31) / 32, 2), dim3(16, 16)>>>(L, nM);
    convert_A2<<<(2 * AROWS * SH + 255) / 256, 256>>>();
    fold_x<<<dim3(SH / 32, D_DIM / 32, B_BATCH), 256>>>(x);

    dim3 grid(D_DIM / 128, 10, B_BATCH);
    gemm_mma<<<grid, 256, SMEM_G>>>(out_trunc, L, nM);

    int btot = B_BATCH * nM * (D_DIM / 4);
    butterfly<<<(btot + 255) / 256, 256>>>(out_recon, L, nM);
}

// round 7
// speedup vs baseline: 4.0708x; 1.0022x over previous
#include <cuda_runtime.h>
#include <cuda_fp16.h>
#include <cuda_bf16.h>
#include <math.h>
#include <stdint.h>

#define B_BATCH 64
#define S_DIM   576
#define SH      288            // folded K (e/o each)
#define D_DIM   1024
#define AROWS   640            // padded rows per parity: [trunc | pad | M at 320..320+nM]
#define MOFF    320            // row offset of Me/Mo block

// ---------------- scratch (no allocs allowed) ----------------
__device__ float         g_A2[2 * AROWS * SH];        // fp32 C-rows (input to build_M2)
__device__ float         g_ClT[S_DIM * S_DIM];        // ClT[i*L + k] = Cl[k,i]
__device__ __nv_bfloat16 g_Ah2[2 * AROWS * SH];
__device__ __nv_bfloat16 g_Al2[2 * AROWS * SH];
__device__ __nv_bfloat16 g_Bh[(size_t)2 * B_BATCH * D_DIM * SH];  // [p][b][d][s]
__device__ __nv_bfloat16 g_Bl[(size_t)2 * B_BATCH * D_DIM * SH];
__device__ float         g_y[(size_t)2 * B_BATCH * SH * D_DIM];   // ye / yo scratch

// ---------------- helpers ----------------
__device__ __forceinline__ uint32_t smem_u32(const void* p) {
    uint32_t a;
    asm("{ .reg .u64 t; cvta.to.shared.u64 t, %1; cvt.u32.u64 %0, t; }" : "=r"(a) : "l"(p));
    return a;
}
__device__ __forceinline__ void cp16(uint32_t dst, const void* src) {
    asm volatile("cp.async.cg.shared.global [%0], [%1], 16;" :: "r"(dst), "l"(src));
}
#define CP_COMMIT() asm volatile("cp.async.commit_group;" ::: "memory")
#define CP_WAIT1()  asm volatile("cp.async.wait_group 1;" ::: "memory")

__device__ __forceinline__ void ldsm_x4(uint32_t& r0, uint32_t& r1, uint32_t& r2,
                                        uint32_t& r3, uint32_t addr) {
    asm volatile("ldmatrix.sync.aligned.m8n8.x4.shared.b16 {%0,%1,%2,%3}, [%4];"
                 : "=r"(r0), "=r"(r1), "=r"(r2), "=r"(r3) : "r"(addr));
}
__device__ __forceinline__ void mma16816(float* d, const uint32_t* a,
                                         uint32_t b0, uint32_t b1) {
    asm volatile("mma.sync.aligned.m16n8k16.row.col.f32.bf16.bf16.f32 "
                 "{%0,%1,%2,%3}, {%4,%5,%6,%7}, {%8,%9}, {%0,%1,%2,%3};"
                 : "+f"(d[0]), "+f"(d[1]), "+f"(d[2]), "+f"(d[3])
                 : "r"(a[0]), "r"(a[1]), "r"(a[2]), "r"(a[3]), "r"(b0), "r"(b1));
}
#define SWZ(x) ((x) ^ (((x) >> 3) & 0x70))

// ---------------- basis build ----------------
__device__ __forceinline__ float dct_entry(int n, int k, int i) {
    float a   = (float)(M_PI / (double)n);
    float t   = a * ((float)i + 0.5f);
    float arg = t * (float)k;
    float c   = (float)cos((double)arg);
    float sc  = (k == 0) ? sqrtf(1.0f / (float)n) : sqrtf(2.0f / (float)n);
    return c * sc;
}

// One kernel: fills C-rows (fp32 + bf16 hi/lo), zeros pad/M bf16 regions, fills ClT.
__global__ void prep_basis(int L) {
    const int total1 = 2 * AROWS * SH;           // A2 full index space
    const int total  = total1 + L * L;           // + ClT
    for (int i = blockIdx.x * blockDim.x + threadIdx.x; i < total;
         i += gridDim.x * blockDim.x) {
        if (i < total1) {
            int p   = i / (AROWS * SH);
            int rem = i - p * (AROWS * SH);
            int row = rem / SH, s = rem - row * SH;
            int nTp = (L + 1 - p) >> 1;
            if (row < nTp) {
                float v = dct_entry(S_DIM, 2 * row + p, s);
                g_A2[i] = v;
                __nv_bfloat16 h = __float2bfloat16(v);
                g_Ah2[i] = h;
                g_Al2[i] = __float2bfloat16(v - __bfloat162float(h));
            } else {
                // pad region + M region: zero bf16 (M rows overwritten by build_M2)
                g_Ah2[i] = __float2bfloat16(0.0f);
                g_Al2[i] = __float2bfloat16(0.0f);
            }
        } else {
            int j = i - total1;
            int ii = j / L, k = j - ii * L;
            g_ClT[ii * L + k] = dct_entry(L, k, ii);
        }
    }
}

// Mp[l,s] = sum_{k=2j+p < L} Cl[k,l] * C[k,s] -> bf16 hi/lo at A2[p][MOFF+l][s]
__global__ void build_M2(int L, int nM) {
    __shared__ float Ts[32][33];
    __shared__ float Cs[32][33];
    int p = blockIdx.z;
    int nK = (L + 1 - p) >> 1;
    const float* Cbase = g_A2 + (size_t)p * AROWS * SH;
    int tx = threadIdx.x, ty = threadIdx.y;       // 16x16
    int lin = ty * 16 + tx;
    int l0 = blockIdx.y * 32, s0 = blockIdx.x * 32;
    float acc00 = 0.f, acc01 = 0.f, acc10 = 0.f, acc11 = 0.f;
    for (int k0 = 0; k0 < nK; k0 += 32) {
        #pragma unroll
        for (int q = 0; q < 4; q++) {
            int e = lin + q * 256;
            int i = e >> 5, j = e & 31;
            int l = l0 + i, jj = k0 + j;
            Ts[i][j] = (l < nM && jj < nK) ? g_ClT[l * L + 2 * jj + p] : 0.0f;
            int j2 = k0 + i, s = s0 + j;
            Cs[i][j] = (j2 < nK && s < SH) ? Cbase[(size_t)j2 * SH + s] : 0.0f;
        }
        __syncthreads();
        #pragma unroll
        for (int kk = 0; kk < 32; kk++) {
            float a0 = Ts[ty * 2][kk], a1 = Ts[ty * 2 + 1][kk];
            float b0 = Cs[kk][tx * 2], b1 = Cs[kk][tx * 2 + 1];
            acc00 = fmaf(a0, b0, acc00); acc01 = fmaf(a0, b1, acc01);
            acc10 = fmaf(a1, b0, acc10); acc11 = fmaf(a1, b1, acc11);
        }
        __syncthreads();
    }
    size_t obase = (size_t)p * AROWS * SH + (size_t)MOFF * SH;
    int l = l0 + ty * 2, s = s0 + tx * 2;
    #pragma unroll
    for (int dl = 0; dl < 2; dl++) {
        #pragma unroll
        for (int ds = 0; ds < 2; ds++) {
            float v = (dl == 0) ? (ds == 0 ? acc00 : acc01)
                                : (ds == 0 ? acc10 : acc11);
            if (l + dl < nM && s + ds < SH) {
                size_t idx = obase + (size_t)(l + dl) * SH + (s + ds);
                __nv_bfloat16 h = __float2bfloat16(v);
                g_Ah2[idx] = h;
                g_Al2[idx] = __float2bfloat16(v - __bfloat162float(h));
            }
        }
    }
}

// x[b][s][d] fp32 -> e/o fold + transpose + hi/lo split: g_B?[p][b][d][s<288]
__global__ void fold_x(const float* __restrict__ x) {
    __shared__ float t0[32][33];
    __shared__ float t1[32][33];
    int b = blockIdx.z;
    int s0 = blockIdx.x * 32, d0 = blockIdx.y * 32;
    int lane = threadIdx.x & 31, row8 = threadIdx.x >> 5;
    #pragma unroll
    for (int r = 0; r < 4; r++) {
        int i = row8 + 8 * r;
        t0[i][lane] = x[((size_t)b * S_DIM + s0 + i) * D_DIM + d0 + lane];
        t1[i][lane] = x[((size_t)b * S_DIM + (S_DIM - 1 - (s0 + i))) * D_DIM + d0 + lane];
    }
    __syncthreads();
    #pragma unroll
    for (int r = 0; r < 4; r++) {
        int i = row8 + 8 * r;                 // d index within tile
        float a = t0[lane][i], c = t1[lane][i];
        float e = a + c, o = a - c;
        __nv_bfloat16 eh = __float2bfloat16(e);
        __nv_bfloat16 el = __float2bfloat16(e - __bfloat162float(eh));
        __nv_bfloat16 oh = __float2bfloat16(o);
        __nv_bfloat16 ol = __float2bfloat16(o - __bfloat162float(oh));
        size_t de   = ((size_t)b * D_DIM + d0 + i) * SH + s0 + lane;
        size_t doff = ((size_t)(B_BATCH + b) * D_DIM + d0 + i) * SH + s0 + lane;
        g_Bh[de]   = eh;  g_Bl[de]   = el;
        g_Bh[doff] = oh;  g_Bl[doff] = ol;
    }
}

// ---------------- main HMMA GEMM ----------------
#define BK          48
#define STAGES      3
#define STAGE_BYTES 32768
#define SMEM_G      (STAGES * STAGE_BYTES)
#define KITERS      18             // 3 terms * 6 chunks of 48

__device__ __forceinline__ void load_stage(uint32_t sbase, int slot, int j,
                                           int rowBase, int colBase,
                                           const __nv_bfloat16* Ah,
                                           const __nv_bfloat16* Al,
                                           const __nv_bfloat16* Bh,
                                           const __nv_bfloat16* Bl, int tid) {
    int t  = j / 6;                 // 0: Ah*Bh  1: Ah*Bl  2: Al*Bh
    int k0 = (j - t * 6) * BK;
    const __nv_bfloat16* Asrc = (t < 2) ? Ah : Al;
    const __nv_bfloat16* Bsrc = (t == 1) ? Bl : Bh;
    uint32_t sA = sbase + slot * STAGE_BYTES;
    uint32_t sB = sA + 16384;
    #pragma unroll
    for (int q = 0; q < 3; q++) {
        int c = tid + q * 256;
        int row = c / 6, ku = c % 6;
        cp16(sA + SWZ(row * 128 + ku * 16),
             Asrc + (size_t)(rowBase + row) * SH + k0 + ku * 8);
        cp16(sB + SWZ(row * 128 + ku * 16),
             Bsrc + (size_t)(colBase + row) * SH + k0 + ku * 8);
    }
}

__global__ __launch_bounds__(256, 2) void gemm_mma(float* __restrict__ out_trunc,
                                                   int L, int nM) {
    extern __shared__ char dsm[];
    uint32_t sbase = smem_u32(dsm);
    const int tid  = threadIdx.x;
    const int warp = tid >> 5;
    const int lane = tid & 31;
    const int b = blockIdx.z;
    const int p = blockIdx.y / 5;
    const int rowBase = (blockIdx.y % 5) * 128;
    const int colBase = blockIdx.x * 128;
    const int nT = (L + 1 - p) >> 1;

    const __nv_bfloat16* Ah = g_Ah2 + (size_t)p * AROWS * SH;
    const __nv_bfloat16* Al = g_Al2 + (size_t)p * AROWS * SH;
    const __nv_bfloat16* Bh = g_Bh + ((size_t)p * B_BATCH + b) * D_DIM * SH;
    const __nv_bfloat16* Bl = g_Bl + ((size_t)p * B_BATCH + b) * D_DIM * SH;

    const int mBase = (warp & 1) * 64;
    const int nBase = (warp >> 1) * 32;

    float acc[4][4][4];
    #pragma unroll
    for (int mt = 0; mt < 4; mt++)
        #pragma unroll
        for (int nt = 0; nt < 4; nt++)
            #pragma unroll
            for (int i = 0; i < 4; i++) acc[mt][nt][i] = 0.0f;

    load_stage(sbase, 0, 0, rowBase, colBase, Ah, Al, Bh, Bl, tid); CP_COMMIT();
    load_stage(sbase, 1, 1, rowBase, colBase, Ah, Al, Bh, Bl, tid); CP_COMMIT();

    const int aRow  = lane & 15;
    const int aColB = (lane >> 4) * 16;
    const int bRow  = (lane & 7) + ((lane >> 4) & 1) * 8;
    const int bColB = ((lane >> 3) & 1) * 16;

    for (int i = 0; i < KITERS; i++) {
        int slot = i % 3;
        CP_WAIT1();
        __syncthreads();

        uint32_t sA = sbase + slot * STAGE_BYTES;
        uint32_t sB = sA + 16384;

        #pragma unroll
        for (int ks = 0; ks < 3; ks++) {
            uint32_t afr[4][4];
            #pragma unroll
            for (int mt = 0; mt < 4; mt++) {
                int off = (mBase + mt * 16 + aRow) * 128 + ks * 32 + aColB;
                ldsm_x4(afr[mt][0], afr[mt][1], afr[mt][2], afr[mt][3], sA + SWZ(off));
            }
            uint32_t bfr[8];
            #pragma unroll
            for (int nt2 = 0; nt2 < 2; nt2++) {
                int off = (nBase + nt2 * 16 + bRow) * 128 + ks * 32 + bColB;
                ldsm_x4(bfr[nt2 * 4 + 0], bfr[nt2 * 4 + 1],
                        bfr[nt2 * 4 + 2], bfr[nt2 * 4 + 3], sB + SWZ(off));
            }
            #pragma unroll
            for (int mt = 0; mt < 4; mt++)
                #pragma unroll
                for (int nt = 0; nt < 4; nt++)
                    mma16816(acc[mt][nt], afr[mt], bfr[nt * 2], bfr[nt * 2 + 1]);
        }

        int j = i + 2;
        if (j < KITERS)
            load_stage(sbase, j % 3, j, rowBase, colBase, Ah, Al, Bh, Bl, tid);
        CP_COMMIT();
    }

    // ---------------- epilogue ----------------
    float* ybase = g_y + ((size_t)p * B_BATCH + b) * SH * D_DIM;
    #pragma unroll
    for (int mt = 0; mt < 4; mt++) {
        #pragma unroll
        for (int nt = 0; nt < 4; nt++) {
            int rA = rowBase + mBase + mt * 16 + (lane >> 2);
            int cc = colBase + nBase + nt * 8 + (lane & 3) * 2;
            #pragma unroll
            for (int h = 0; h < 2; h++) {
                int r = rA + h * 8;
                float2 v = make_float2(acc[mt][nt][h * 2 + 0], acc[mt][nt][h * 2 + 1]);
                if (r < nT) {
                    int tr = 2 * r + p;
                    *reinterpret_cast<float2*>(
                        &out_trunc[((size_t)b * L + tr) * D_DIM + cc]) = v;
                } else if (r >= MOFF && r < MOFF + nM) {
                    *reinterpret_cast<float2*>(
                        &ybase[(size_t)(r - MOFF) * D_DIM + cc]) = v;
                }
            }
        }
    }
}

// recon[l] = fp16(ye+yo), recon[L-1-l] = fp16(ye-yo)
__global__ void butterfly(float* __restrict__ out_recon, int L, int nM) {
    int idx = blockIdx.x * blockDim.x + threadIdx.x;
    int total = B_BATCH * nM * (D_DIM / 4);
    if (idx >= total) return;
    int d4 = idx & (D_DIM / 4 - 1);
    int l  = (idx / (D_DIM / 4)) % nM;
    int b  = idx / ((D_DIM / 4) * nM);
    int d  = d4 * 4;
    const float4 ye = *reinterpret_cast<const float4*>(
        &g_y[((size_t)b * SH + l) * D_DIM + d]);
    const float4 yo = *reinterpret_cast<const float4*>(
        &g_y[((size_t)(B_BATCH + b) * SH + l) * D_DIM + d]);
    float4 s, f;
    s.x = __half2float(__float2half_rn(ye.x + yo.x));
    s.y = __half2float(__float2half_rn(ye.y + yo.y));
    s.z = __half2float(__float2half_rn(ye.z + yo.z));
    s.w = __half2float(__float2half_rn(ye.w + yo.w));
    *reinterpret_cast<float4*>(&out_recon[((size_t)b * L + l) * D_DIM + d]) = s;
    int l2 = L - 1 - l;
    if (l2 != l) {
        f.x = __half2float(__float2half_rn(ye.x - yo.x));
        f.y = __half2float(__float2half_rn(ye.y - yo.y));
        f.z = __half2float(__float2half_rn(ye.z - yo.z));
        f.w = __half2float(__float2half_rn(ye.w - yo.w));
        *reinterpret_cast<float4*>(&out_recon[((size_t)b * L + l2) * D_DIM + d]) = f;
    }
}

// ---------------- launch ----------------
static cudaStream_t g_s2 = 0;
static cudaEvent_t  g_evFork = 0, g_evJoin = 0;

extern "C" void kernel_launch(void* const* d_in, const int* in_sizes, int n_in,
                              void* d_out, int out_size) {
    const float* x = (const float*)d_in[0];
    const int L  = out_size / (2 * B_BATCH * D_DIM);
    const int nM = (L + 1) >> 1;

    float* out_recon = (float*)d_out;
    float* out_trunc = (float*)d_out + (size_t)B_BATCH * L * D_DIM;

    if (!g_s2) {     // first call is the uncaptured correctness run
        cudaStreamCreateWithFlags(&g_s2, cudaStreamNonBlocking);
        cudaEventCreateWithFlags(&g_evFork, cudaEventDisableTiming);
        cudaEventCreateWithFlags(&g_evJoin, cudaEventDisableTiming);
        cudaFuncSetAttribute(gemm_mma, cudaFuncAttributeMaxDynamicSharedMemorySize,
                             SMEM_G);
    }

    // fork: A-side build chain on side stream, B-side fold on capture stream
    cudaEventRecord(g_evFork, 0);
    cudaStreamWaitEvent(g_s2, g_evFork, 0);

    prep_basis<<<512, 256, 0, g_s2>>>(L);
    build_M2<<<dim3(SH / 32, (nM + 31) / 32, 2), dim3(16, 16), 0, g_s2>>>(L, nM);

    fold_x<<<dim3(SH / 32, D_DIM / 32, B_BATCH), 256>>>(x);

    // join
    cudaEventRecord(g_evJoin, g_s2);
    cudaStreamWaitEvent(0, g_evJoin, 0);

    dim3 grid(D_DIM / 128, 10, B_BATCH);
    gemm_mma<<<grid, 256, SMEM_G>>>(out_trunc, L, nM);

    int btot = B_BATCH * nM * (D_DIM / 4);
    butterfly<<<(btot + 255) / 256, 256>>>(out_recon, L, nM);
}

// round 8
// speedup vs baseline: 4.0989x; 1.0069x over previous
#include <cuda_runtime.h>
#include <cuda_fp16.h>
#include <cuda_bf16.h>
#include <math.h>
#include <stdint.h>

#define B_BATCH 64
#define S_DIM   576
#define SH      288            // folded K (e/o each)
#define D_DIM   1024
#define AROWS   640            // padded rows per parity: [trunc | pad | M at 320..320+nM]
#define MOFF    320            // row offset of Me/Mo block
#define NTILES  5120           // 8 colblocks * 10 (p,rowblock) * 64 batches
#define GRID_P  304            // 2 CTAs/SM * 152 SMs

// ---------------- scratch (no allocs allowed) ----------------
__device__ float         g_A2[2 * AROWS * SH];        // fp32 C-rows (input to build_M2)
__device__ float         g_ClT[S_DIM * S_DIM];        // ClT[i*L + k] = Cl[k,i]
__device__ __nv_bfloat16 g_Ah2[2 * AROWS * SH];
__device__ __nv_bfloat16 g_Al2[2 * AROWS * SH];
__device__ __nv_bfloat16 g_Bh[(size_t)2 * B_BATCH * D_DIM * SH];  // [p][b][d][s]
__device__ __nv_bfloat16 g_Bl[(size_t)2 * B_BATCH * D_DIM * SH];
__device__ float         g_y[(size_t)2 * B_BATCH * SH * D_DIM];   // ye / yo scratch

// ---------------- helpers ----------------
__device__ __forceinline__ uint32_t smem_u32(const void* p) {
    uint32_t a;
    asm("{ .reg .u64 t; cvta.to.shared.u64 t, %1; cvt.u32.u64 %0, t; }" : "=r"(a) : "l"(p));
    return a;
}
__device__ __forceinline__ void cp16(uint32_t dst, const void* src) {
    asm volatile("cp.async.cg.shared.global [%0], [%1], 16;" :: "r"(dst), "l"(src));
}
#define CP_COMMIT() asm volatile("cp.async.commit_group;" ::: "memory")
#define CP_WAIT1()  asm volatile("cp.async.wait_group 1;" ::: "memory")

__device__ __forceinline__ void ldsm_x4(uint32_t& r0, uint32_t& r1, uint32_t& r2,
                                        uint32_t& r3, uint32_t addr) {
    asm volatile("ldmatrix.sync.aligned.m8n8.x4.shared.b16 {%0,%1,%2,%3}, [%4];"
                 : "=r"(r0), "=r"(r1), "=r"(r2), "=r"(r3) : "r"(addr));
}
__device__ __forceinline__ void mma16816(float* d, const uint32_t* a,
                                         uint32_t b0, uint32_t b1) {
    asm volatile("mma.sync.aligned.m16n8k16.row.col.f32.bf16.bf16.f32 "
                 "{%0,%1,%2,%3}, {%4,%5,%6,%7}, {%8,%9}, {%0,%1,%2,%3};"
                 : "+f"(d[0]), "+f"(d[1]), "+f"(d[2]), "+f"(d[3])
                 : "r"(a[0]), "r"(a[1]), "r"(a[2]), "r"(a[3]), "r"(b0), "r"(b1));
}
#define SWZ(x) ((x) ^ (((x) >> 3) & 0x70))

// ---------------- basis build ----------------
__device__ __forceinline__ float dct_entry(int n, int k, int i) {
    float a   = (float)(M_PI / (double)n);
    float t   = a * ((float)i + 0.5f);
    float arg = t * (float)k;
    float c   = (float)cos((double)arg);
    float sc  = (k == 0) ? sqrtf(1.0f / (float)n) : sqrtf(2.0f / (float)n);
    return c * sc;
}

// Fills C-rows (fp32 + bf16 hi/lo), zeros pad/M bf16 regions, fills ClT.
__global__ void prep_basis(int L) {
    const int total1 = 2 * AROWS * SH;
    const int total  = total1 + L * L;
    for (int i = blockIdx.x * blockDim.x + threadIdx.x; i < total;
         i += gridDim.x * blockDim.x) {
        if (i < total1) {
            int p   = i / (AROWS * SH);
            int rem = i - p * (AROWS * SH);
            int row = rem / SH, s = rem - row * SH;
            int nTp = (L + 1 - p) >> 1;
            if (row < nTp) {
                float v = dct_entry(S_DIM, 2 * row + p, s);
                g_A2[i] = v;
                __nv_bfloat16 h = __float2bfloat16(v);
                g_Ah2[i] = h;
                g_Al2[i] = __float2bfloat16(v - __bfloat162float(h));
            } else {
                g_Ah2[i] = __float2bfloat16(0.0f);
                g_Al2[i] = __float2bfloat16(0.0f);
            }
        } else {
            int j = i - total1;
            int ii = j / L, k = j - ii * L;
            g_ClT[ii * L + k] = dct_entry(L, k, ii);
        }
    }
}

// Mp[l,s] = sum_{k=2j+p < L} Cl[k,l] * C[k,s] -> bf16 hi/lo at A2[p][MOFF+l][s]
__global__ void build_M2(int L, int nM) {
    __shared__ float Ts[32][33];
    __shared__ float Cs[32][33];
    int p = blockIdx.z;
    int nK = (L + 1 - p) >> 1;
    const float* Cbase = g_A2 + (size_t)p * AROWS * SH;
    int tx = threadIdx.x, ty = threadIdx.y;       // 16x16
    int lin = ty * 16 + tx;
    int l0 = blockIdx.y * 32, s0 = blockIdx.x * 32;
    float acc00 = 0.f, acc01 = 0.f, acc10 = 0.f, acc11 = 0.f;
    for (int k0 = 0; k0 < nK; k0 += 32) {
        #pragma unroll
        for (int q = 0; q < 4; q++) {
            int e = lin + q * 256;
            int i = e >> 5, j = e & 31;
            int l = l0 + i, jj = k0 + j;
            Ts[i][j] = (l < nM && jj < nK) ? g_ClT[l * L + 2 * jj + p] : 0.0f;
            int j2 = k0 + i, s = s0 + j;
            Cs[i][j] = (j2 < nK && s < SH) ? Cbase[(size_t)j2 * SH + s] : 0.0f;
        }
        __syncthreads();
        #pragma unroll
        for (int kk = 0; kk < 32; kk++) {
            float a0 = Ts[ty * 2][kk], a1 = Ts[ty * 2 + 1][kk];
            float b0 = Cs[kk][tx * 2], b1 = Cs[kk][tx * 2 + 1];
            acc00 = fmaf(a0, b0, acc00); acc01 = fmaf(a0, b1, acc01);
            acc10 = fmaf(a1, b0, acc10); acc11 = fmaf(a1, b1, acc11);
        }
        __syncthreads();
    }
    size_t obase = (size_t)p * AROWS * SH + (size_t)MOFF * SH;
    int l = l0 + ty * 2, s = s0 + tx * 2;
    #pragma unroll
    for (int dl = 0; dl < 2; dl++) {
        #pragma unroll
        for (int ds = 0; ds < 2; ds++) {
            float v = (dl == 0) ? (ds == 0 ? acc00 : acc01)
                                : (ds == 0 ? acc10 : acc11);
            if (l + dl < nM && s + ds < SH) {
                size_t idx = obase + (size_t)(l + dl) * SH + (s + ds);
                __nv_bfloat16 h = __float2bfloat16(v);
                g_Ah2[idx] = h;
                g_Al2[idx] = __float2bfloat16(v - __bfloat162float(h));
            }
        }
    }
}

// x[b][s][d] fp32 -> e/o fold + transpose + hi/lo split: g_B?[p][b][d][s<288]
__global__ void fold_x(const float* __restrict__ x) {
    __shared__ float t0[32][33];
    __shared__ float t1[32][33];
    int b = blockIdx.z;
    int s0 = blockIdx.x * 32, d0 = blockIdx.y * 32;
    int lane = threadIdx.x & 31, row8 = threadIdx.x >> 5;
    #pragma unroll
    for (int r = 0; r < 4; r++) {
        int i = row8 + 8 * r;
        t0[i][lane] = x[((size_t)b * S_DIM + s0 + i) * D_DIM + d0 + lane];
        t1[i][lane] = x[((size_t)b * S_DIM + (S_DIM - 1 - (s0 + i))) * D_DIM + d0 + lane];
    }
    __syncthreads();
    #pragma unroll
    for (int r = 0; r < 4; r++) {
        int i = row8 + 8 * r;                 // d index within tile
        float a = t0[lane][i], c = t1[lane][i];
        float e = a + c, o = a - c;
        __nv_bfloat16 eh = __float2bfloat16(e);
        __nv_bfloat16 el = __float2bfloat16(e - __bfloat162float(eh));
        __nv_bfloat16 oh = __float2bfloat16(o);
        __nv_bfloat16 ol = __float2bfloat16(o - __bfloat162float(oh));
        size_t de   = ((size_t)b * D_DIM + d0 + i) * SH + s0 + lane;
        size_t doff = ((size_t)(B_BATCH + b) * D_DIM + d0 + i) * SH + s0 + lane;
        g_Bh[de]   = eh;  g_Bl[de]   = el;
        g_Bh[doff] = oh;  g_Bl[doff] = ol;
    }
}

// ---------------- persistent HMMA GEMM ----------------
#define BK          48
#define STAGE_BYTES 32768
#define SMEM_G      (3 * STAGE_BYTES)
#define KITERS      18             // 3 terms * 6 chunks of 48

struct LdCtx {
    const __nv_bfloat16 *pAh, *pAl, *pBh, *pBl;   // tile-local bases (row folded in)
};

__device__ __forceinline__ void set_ctx(LdCtx& c, int t) {
    int x = t & 7;
    int y = (t >> 3) % 10;
    int b = t / 80;
    int p = y / 5;
    int rowBase = (y % 5) * 128;
    int colBase = x * 128;
    size_t aoff = (size_t)p * AROWS * SH + (size_t)rowBase * SH;
    size_t boff = ((size_t)(p * B_BATCH + b) * D_DIM + colBase) * SH;
    c.pAh = g_Ah2 + aoff;
    c.pAl = g_Al2 + aoff;
    c.pBh = g_Bh + boff;
    c.pBl = g_Bl + boff;
}

__device__ __forceinline__ void load_stage(uint32_t sbase, int slot, int j,
                                           const LdCtx& c, int tid) {
    int t  = j / 6;                 // 0: Ah*Bh  1: Ah*Bl  2: Al*Bh
    int k0 = (j - t * 6) * BK;
    const __nv_bfloat16* Asrc = (t < 2) ? c.pAh : c.pAl;
    const __nv_bfloat16* Bsrc = (t == 1) ? c.pBl : c.pBh;
    uint32_t sA = sbase + slot * STAGE_BYTES;
    uint32_t sB = sA + 16384;
    #pragma unroll
    for (int q = 0; q < 3; q++) {
        int cix = tid + q * 256;
        int row = cix / 6, ku = cix % 6;
        cp16(sA + SWZ(row * 128 + ku * 16),
             Asrc + (size_t)row * SH + k0 + ku * 8);
        cp16(sB + SWZ(row * 128 + ku * 16),
             Bsrc + (size_t)row * SH + k0 + ku * 8);
    }
}

__global__ __launch_bounds__(256, 2) void gemm_mma(float* __restrict__ out_trunc,
                                                   int L, int nM) {
    extern __shared__ char dsm[];
    uint32_t sbase = smem_u32(dsm);
    const int tid  = threadIdx.x;
    const int warp = tid >> 5;
    const int lane = tid & 31;
    const int stride = gridDim.x;

    const int mBase = (warp & 1) * 64;
    const int nBase = (warp >> 1) * 32;
    const int aRow  = lane & 15;
    const int aColB = (lane >> 4) * 16;
    const int bRow  = (lane & 7) + ((lane >> 4) & 1) * 8;
    const int bColB = ((lane >> 3) & 1) * 16;

    // load-side state, runs 2 iterations ahead
    int t_ld = blockIdx.x;
    int j_ld = 0;
    int slot_ld = 0;
    LdCtx ctx;
    if (t_ld < NTILES) set_ctx(ctx, t_ld);

    #pragma unroll
    for (int q = 0; q < 2; q++) {        // prologue: fill 2 stages
        if (t_ld < NTILES) load_stage(sbase, slot_ld, j_ld, ctx, tid);
        CP_COMMIT();
        slot_ld = (slot_ld == 2) ? 0 : slot_ld + 1;
        if (++j_ld == KITERS) {
            j_ld = 0; t_ld += stride;
            if (t_ld < NTILES) set_ctx(ctx, t_ld);
        }
    }

    int slot_cp = 0;
    for (int t_cp = blockIdx.x; t_cp < NTILES; t_cp += stride) {
        float acc[4][4][4];
        #pragma unroll
        for (int mt = 0; mt < 4; mt++)
            #pragma unroll
            for (int nt = 0; nt < 4; nt++)
                #pragma unroll
                for (int i = 0; i < 4; i++) acc[mt][nt][i] = 0.0f;

        for (int j = 0; j < KITERS; j++) {
            CP_WAIT1();
            __syncthreads();

            uint32_t sA = sbase + slot_cp * STAGE_BYTES;
            uint32_t sB = sA + 16384;

            #pragma unroll
            for (int ks = 0; ks < 3; ks++) {
                uint32_t afr[4][4];
                #pragma unroll
                for (int mt = 0; mt < 4; mt++) {
                    int off = (mBase + mt * 16 + aRow) * 128 + ks * 32 + aColB;
                    ldsm_x4(afr[mt][0], afr[mt][1], afr[mt][2], afr[mt][3],
                            sA + SWZ(off));
                }
                uint32_t bfr[8];
                #pragma unroll
                for (int nt2 = 0; nt2 < 2; nt2++) {
                    int off = (nBase + nt2 * 16 + bRow) * 128 + ks * 32 + bColB;
                    ldsm_x4(bfr[nt2 * 4 + 0], bfr[nt2 * 4 + 1],
                            bfr[nt2 * 4 + 2], bfr[nt2 * 4 + 3], sB + SWZ(off));
                }
                #pragma unroll
                for (int mt = 0; mt < 4; mt++)
                    #pragma unroll
                    for (int nt = 0; nt < 4; nt++)
                        mma16816(acc[mt][nt], afr[mt], bfr[nt * 2], bfr[nt * 2 + 1]);
            }

            // feed pipeline (2 ahead), possibly into the next tile
            if (t_ld < NTILES) load_stage(sbase, slot_ld, j_ld, ctx, tid);
            CP_COMMIT();
            slot_ld = (slot_ld == 2) ? 0 : slot_ld + 1;
            if (++j_ld == KITERS) {
                j_ld = 0; t_ld += stride;
                if (t_ld < NTILES) set_ctx(ctx, t_ld);
            }
            slot_cp = (slot_cp == 2) ? 0 : slot_cp + 1;
        }

        // ---- epilogue (registers -> gmem; no smem, no barrier) ----
        int xx = t_cp & 7;
        int yy = (t_cp >> 3) % 10;
        int bb = t_cp / 80;
        int pp = yy / 5;
        int rowBase = (yy % 5) * 128;
        int colBase = xx * 128;
        int nT = (L + 1 - pp) >> 1;
        float* ybase = g_y + ((size_t)pp * B_BATCH + bb) * SH * D_DIM;

        #pragma unroll
        for (int mt = 0; mt < 4; mt++) {
            #pragma unroll
            for (int nt = 0; nt < 4; nt++) {
                int rA = rowBase + mBase + mt * 16 + (lane >> 2);
                int cc = colBase + nBase + nt * 8 + (lane & 3) * 2;
                #pragma unroll
                for (int h = 0; h < 2; h++) {
                    int r = rA + h * 8;
                    float2 v = make_float2(acc[mt][nt][h * 2 + 0],
                                           acc[mt][nt][h * 2 + 1]);
                    if (r < nT) {
                        int tr = 2 * r + pp;
                        *reinterpret_cast<float2*>(
                            &out_trunc[((size_t)bb * L + tr) * D_DIM + cc]) = v;
                    } else if (r >= MOFF && r < MOFF + nM) {
                        *reinterpret_cast<float2*>(
                            &ybase[(size_t)(r - MOFF) * D_DIM + cc]) = v;
                    }
                }
            }
        }
    }
}

// recon[l] = fp16(ye+yo), recon[L-1-l] = fp16(ye-yo)
__global__ void butterfly(float* __restrict__ out_recon, int L, int nM) {
    int idx = blockIdx.x * blockDim.x + threadIdx.x;
    int total = B_BATCH * nM * (D_DIM / 4);
    if (idx >= total) return;
    int d4 = idx & (D_DIM / 4 - 1);
    int l  = (idx / (D_DIM / 4)) % nM;
    int b  = idx / ((D_DIM / 4) * nM);
    int d  = d4 * 4;
    const float4 ye = *reinterpret_cast<const float4*>(
        &g_y[((size_t)b * SH + l) * D_DIM + d]);
    const float4 yo = *reinterpret_cast<const float4*>(
        &g_y[((size_t)(B_BATCH + b) * SH + l) * D_DIM + d]);
    float4 s, f;
    s.x = __half2float(__float2half_rn(ye.x + yo.x));
    s.y = __half2float(__float2half_rn(ye.y + yo.y));
    s.z = __half2float(__float2half_rn(ye.z + yo.z));
    s.w = __half2float(__float2half_rn(ye.w + yo.w));
    *reinterpret_cast<float4*>(&out_recon[((size_t)b * L + l) * D_DIM + d]) = s;
    int l2 = L - 1 - l;
    if (l2 != l) {
        f.x = __half2float(__float2half_rn(ye.x - yo.x));
        f.y = __half2float(__float2half_rn(ye.y - yo.y));
        f.z = __half2float(__float2half_rn(ye.z - yo.z));
        f.w = __half2float(__float2half_rn(ye.w - yo.w));
        *reinterpret_cast<float4*>(&out_recon[((size_t)b * L + l2) * D_DIM + d]) = f;
    }
}

// ---------------- launch ----------------
static cudaStream_t g_s2 = 0;
static cudaEvent_t  g_evFork = 0, g_evJoin = 0;

extern "C" void kernel_launch(void* const* d_in, const int* in_sizes, int n_in,
                              void* d_out, int out_size) {
    const float* x = (const float*)d_in[0];
    const int L  = out_size / (2 * B_BATCH * D_DIM);
    const int nM = (L + 1) >> 1;

    float* out_recon = (float*)d_out;
    float* out_trunc = (float*)d_out + (size_t)B_BATCH * L * D_DIM;

    if (!g_s2) {     // first call is the uncaptured correctness run
        cudaStreamCreateWithFlags(&g_s2, cudaStreamNonBlocking);
        cudaEventCreateWithFlags(&g_evFork, cudaEventDisableTiming);
        cudaEventCreateWithFlags(&g_evJoin, cudaEventDisableTiming);
        cudaFuncSetAttribute(gemm_mma, cudaFuncAttributeMaxDynamicSharedMemorySize,
                             SMEM_G);
    }

    // fork: A-side build chain on side stream, B-side fold on capture stream
    cudaEventRecord(g_evFork, 0);
    cudaStreamWaitEvent(g_s2, g_evFork, 0);

    prep_basis<<<512, 256, 0, g_s2>>>(L);
    build_M2<<<dim3(SH / 32, (nM + 31) / 32, 2), dim3(16, 16), 0, g_s2>>>(L, nM);

    fold_x<<<dim3(SH / 32, D_DIM / 32, B_BATCH), 256>>>(x);

    // join
    cudaEventRecord(g_evJoin, g_s2);
    cudaStreamWaitEvent(0, g_evJoin, 0);

    gemm_mma<<<GRID_P, 256, SMEM_G>>>(out_trunc, L, nM);

    int btot = B_BATCH * nM * (D_DIM / 4);
    butterfly<<<(btot + 255) / 256, 256>>>(out_recon, L, nM);
}